// round 12
// baseline (speedup 1.0000x reference)
#include <cuda_runtime.h>
#include <cuda_bf16.h>
#include <math.h>
#include <stdint.h>

// ---------------------------------------------------------------------------
// MultiHeadAttention: B=8, L=1024, D_MODEL=1024, H=16, Dk=64
// Round 12: round-11 (1188us) + ONE change: fused_attn re-tiled to
// 256 threads / 16 q-rows / 2 blocks-per-SM (was 512t / 32 rows / 1 block).
// proj (256t, 2/SM), splits, launches: identical to round 11.
// d_out = [ out (8*1024*1024 f32) | attn_flat ((16*8)*1024*1024 f32) ]
// ---------------------------------------------------------------------------

#define BATCH 8
#define SEQ   1024
#define DMODEL 1024
#define NHEAD 16
#define DK    64
#define MROWS (BATCH * SEQ)          // 8192
#define OUT_ELEMS (MROWS * DMODEL)   // 8388608

#define BKP  40    // 32 + 8 pad (bf16) A tiles (proj)
#define BNP  136   // 128 + 8 pad  B tiles (proj)
#define QKP  72    // 64 + 8 pad   attn Q/K/V tiles

// ---------------- static scratch (no allocations) ----------------
__device__ __nv_bfloat16 g_q_hi[MROWS * DMODEL],  g_q_lo[MROWS * DMODEL];
__device__ __nv_bfloat16 g_k_hi[MROWS * DMODEL],  g_k_lo[MROWS * DMODEL];
__device__ __nv_bfloat16 g_v_hi[MROWS * DMODEL],  g_v_lo[MROWS * DMODEL];
__device__ __nv_bfloat16 g_Wq_hi[DMODEL * DMODEL], g_Wq_lo[DMODEL * DMODEL];
__device__ __nv_bfloat16 g_Wk_hi[DMODEL * DMODEL], g_Wk_lo[DMODEL * DMODEL];
__device__ __nv_bfloat16 g_Wv_hi[DMODEL * DMODEL], g_Wv_lo[DMODEL * DMODEL];
__device__ __nv_bfloat16 g_Wfc_hi[DMODEL * DMODEL], g_Wfc_lo[DMODEL * DMODEL];
__device__ __nv_bfloat16 g_qh_hi[MROWS * DMODEL], g_qh_lo[MROWS * DMODEL];
__device__ __nv_bfloat16 g_kh_hi[MROWS * DMODEL], g_kh_lo[MROWS * DMODEL];
__device__ __nv_bfloat16 g_vh_hi[MROWS * DMODEL], g_vh_lo[MROWS * DMODEL];
__device__ __nv_bfloat16 g_ctx_hi[MROWS * DMODEL], g_ctx_lo[MROWS * DMODEL];

// ---------------------------------------------------------------------------
// PTX helpers
// ---------------------------------------------------------------------------
__device__ __forceinline__ uint32_t smem_u32(const void* p) {
    return (uint32_t)__cvta_generic_to_shared(p);
}

#define LDMX4(r0,r1,r2,r3,addr) \
    asm volatile("ldmatrix.sync.aligned.m8n8.x4.shared.b16 {%0,%1,%2,%3}, [%4];" \
        : "=r"(r0), "=r"(r1), "=r"(r2), "=r"(r3) : "r"(addr))

#define LDMX4T(r0,r1,r2,r3,addr) \
    asm volatile("ldmatrix.sync.aligned.m8n8.x4.trans.shared.b16 {%0,%1,%2,%3}, [%4];" \
        : "=r"(r0), "=r"(r1), "=r"(r2), "=r"(r3) : "r"(addr))

#define MMA16816(c, a, b) \
    asm volatile("mma.sync.aligned.m16n8k16.row.col.f32.bf16.bf16.f32 " \
        "{%0,%1,%2,%3}, {%4,%5,%6,%7}, {%8,%9}, {%0,%1,%2,%3};" \
        : "+f"((c)[0]), "+f"((c)[1]), "+f"((c)[2]), "+f"((c)[3]) \
        : "r"((a)[0]), "r"((a)[1]), "r"((a)[2]), "r"((a)[3]), \
          "r"((b)[0]), "r"((b)[1]))

#define CPA16(dst, src) \
    asm volatile("cp.async.cg.shared.global [%0], [%1], 16;" :: "r"(dst), "l"(src))
#define CPA_COMMIT() asm volatile("cp.async.commit_group;")
#define CPA_WAIT1()  asm volatile("cp.async.wait_group 1;")
#define CPA_WAIT0()  asm volatile("cp.async.wait_group 0;")

__device__ __forceinline__ uint32_t pack_hi(float x, float y) {
    __nv_bfloat162 h;
    h.x = __float2bfloat16(x); h.y = __float2bfloat16(y);
    return *(uint32_t*)&h;
}
__device__ __forceinline__ uint32_t pack_lo(float x, float y) {
    __nv_bfloat16 hx = __float2bfloat16(x), hy = __float2bfloat16(y);
    __nv_bfloat162 l;
    l.x = __float2bfloat16(x - __bfloat162float(hx));
    l.y = __float2bfloat16(y - __bfloat162float(hy));
    return *(uint32_t*)&l;
}

// ---------------------------------------------------------------------------
// Elementwise pre-split: f32 -> (hi, lo) bf16
// ---------------------------------------------------------------------------
__global__ __launch_bounds__(256) void split_kernel(
    const float* __restrict__ in, __nv_bfloat16* __restrict__ hi,
    __nv_bfloat16* __restrict__ lo)
{
    const int i = (blockIdx.x * 256 + threadIdx.x) * 4;
    float4 v = *(const float4*)(in + i);
    __nv_bfloat16 h0 = __float2bfloat16(v.x);
    __nv_bfloat16 h1 = __float2bfloat16(v.y);
    __nv_bfloat16 h2 = __float2bfloat16(v.z);
    __nv_bfloat16 h3 = __float2bfloat16(v.w);
    __nv_bfloat162 hp0; hp0.x = h0; hp0.y = h1;
    __nv_bfloat162 hp1; hp1.x = h2; hp1.y = h3;
    *(__nv_bfloat162*)(hi + i)     = hp0;
    *(__nv_bfloat162*)(hi + i + 2) = hp1;
    __nv_bfloat162 lp0, lp1;
    lp0.x = __float2bfloat16(v.x - __bfloat162float(h0));
    lp0.y = __float2bfloat16(v.y - __bfloat162float(h1));
    lp1.x = __float2bfloat16(v.z - __bfloat162float(h2));
    lp1.y = __float2bfloat16(v.w - __bfloat162float(h3));
    *(__nv_bfloat162*)(lo + i)     = lp0;
    *(__nv_bfloat162*)(lo + i + 2) = lp1;
}

// ---------------------------------------------------------------------------
// Projection GEMM — 256 threads, 64x128 tile, BK=32, 2-stage cp.async,
// 2 blocks/SM (verified round-11 version, unchanged).
// ---------------------------------------------------------------------------
#define PRJ_ABUF (64 * BKP * 2)            // 5120
#define PRJ_BBUF (32 * BNP * 2)            // 8704
#define PRJ_OAHI 0
#define PRJ_OALO (2 * PRJ_ABUF)            // 10240
#define PRJ_OBHI (4 * PRJ_ABUF)            // 20480
#define PRJ_OBLO (PRJ_OBHI + 2 * PRJ_BBUF) // 37888
#define PRJ_SMEM (PRJ_OBLO + 2 * PRJ_BBUF) // 55296

template<bool F32OUT>
__global__ __launch_bounds__(256, 2) void proj_gemm_async(
    const __nv_bfloat16* __restrict__ Ahi_g, const __nv_bfloat16* __restrict__ Alo_g,
    const __nv_bfloat16* __restrict__ Bhi_g, const __nv_bfloat16* __restrict__ Blo_g,
    const float* __restrict__ bias,
    float* __restrict__ Cf, __nv_bfloat16* __restrict__ Chi, __nv_bfloat16* __restrict__ Clo,
    int M, int N, int K)
{
    extern __shared__ __align__(16) char dynsmem[];
    const uint32_t sBase = smem_u32(dynsmem);
    const uint32_t sAhi = sBase + PRJ_OAHI;
    const uint32_t sAlo = sBase + PRJ_OALO;
    const uint32_t sBhi = sBase + PRJ_OBHI;
    const uint32_t sBlo = sBase + PRJ_OBLO;

    const int tid = threadIdx.x;
    const int warp = tid >> 5, lane = tid & 31;
    const int wm = warp & 1, wn = warp >> 1;       // 2 x 4
    const int rowBlock = blockIdx.y * 64;
    const int colBlock = blockIdx.x * 128;

    const int arow = tid >> 2, aseg = tid & 3;
    const long long aGbase = (long long)(rowBlock + arow) * K + aseg * 8;
    const uint32_t aSoff = (uint32_t)(arow * BKP + aseg * 8) * 2;
    const int brow0 = tid >> 4,          bseg0 = tid & 15;
    const int brow1 = (tid + 256) >> 4,  bseg1 = (tid + 256) & 15;
    const long long bGbase0 = (long long)brow0 * N + colBlock + bseg0 * 8;
    const long long bGbase1 = (long long)brow1 * N + colBlock + bseg1 * 8;
    const uint32_t bSoff0 = (uint32_t)(brow0 * BNP + bseg0 * 8) * 2;
    const uint32_t bSoff1 = (uint32_t)(brow1 * BNP + bseg1 * 8) * 2;

    auto load_tile = [&](int kt, int buf) {
        const long long ka  = aGbase + kt * 32;
        const long long kb0 = bGbase0 + (long long)(kt * 32) * N;
        const long long kb1 = bGbase1 + (long long)(kt * 32) * N;
        CPA16(sAhi + buf * PRJ_ABUF + aSoff, Ahi_g + ka);
        CPA16(sAlo + buf * PRJ_ABUF + aSoff, Alo_g + ka);
        CPA16(sBhi + buf * PRJ_BBUF + bSoff0, Bhi_g + kb0);
        CPA16(sBhi + buf * PRJ_BBUF + bSoff1, Bhi_g + kb1);
        CPA16(sBlo + buf * PRJ_BBUF + bSoff0, Blo_g + kb0);
        CPA16(sBlo + buf * PRJ_BBUF + bSoff1, Blo_g + kb1);
        CPA_COMMIT();
    };

    float acc[2][4][4];
    #pragma unroll
    for (int i = 0; i < 2; i++)
        #pragma unroll
        for (int j = 0; j < 4; j++)
            #pragma unroll
            for (int l = 0; l < 4; l++) acc[i][j][l] = 0.f;

    const int alr = (lane & 7) + ((lane >> 3) & 1) * 8;
    const int alc = (lane >> 4) * 8;
    const int bkr = (lane & 7) + ((lane >> 3) & 1) * 8;
    const int bnc = ((lane >> 4) & 1) * 8;

    const int KT = K / 32;
    load_tile(0, 0);
    for (int kt = 0; kt < KT; kt++) {
        const int buf = kt & 1;
        if (kt + 1 < KT) { load_tile(kt + 1, (kt + 1) & 1); CPA_WAIT1(); }
        else             { CPA_WAIT0(); }
        __syncthreads();

        const uint32_t bAhi = sAhi + buf * PRJ_ABUF;
        const uint32_t bAlo = sAlo + buf * PRJ_ABUF;
        const uint32_t bBhi = sBhi + buf * PRJ_BBUF;
        const uint32_t bBlo = sBlo + buf * PRJ_BBUF;

        #pragma unroll
        for (int kk = 0; kk < 32; kk += 16) {
            uint32_t ahi[2][4], alo[2][4];
            #pragma unroll
            for (int ms = 0; ms < 2; ms++) {
                uint32_t off = (uint32_t)((wm * 32 + ms * 16 + alr) * BKP + kk + alc) * 2;
                LDMX4(ahi[ms][0], ahi[ms][1], ahi[ms][2], ahi[ms][3], bAhi + off);
                LDMX4(alo[ms][0], alo[ms][1], alo[ms][2], alo[ms][3], bAlo + off);
            }
            uint32_t bhi[4][2], blo[4][2];
            #pragma unroll
            for (int np = 0; np < 2; np++) {
                uint32_t r0, r1, r2, r3;
                uint32_t off = (uint32_t)((kk + bkr) * BNP + wn * 32 + np * 16 + bnc) * 2;
                LDMX4T(r0, r1, r2, r3, bBhi + off);
                bhi[np*2][0] = r0; bhi[np*2][1] = r1;
                bhi[np*2+1][0] = r2; bhi[np*2+1][1] = r3;
                LDMX4T(r0, r1, r2, r3, bBlo + off);
                blo[np*2][0] = r0; blo[np*2][1] = r1;
                blo[np*2+1][0] = r2; blo[np*2+1][1] = r3;
            }
            #pragma unroll
            for (int ms = 0; ms < 2; ms++)
                #pragma unroll
                for (int ns = 0; ns < 4; ns++) {
                    MMA16816(acc[ms][ns], ahi[ms], bhi[ns]);
                    MMA16816(acc[ms][ns], alo[ms], bhi[ns]);
                    MMA16816(acc[ms][ns], ahi[ms], blo[ns]);
                }
        }
        __syncthreads();
    }

    const int gid = lane >> 2, tig = lane & 3;
    #pragma unroll
    for (int ms = 0; ms < 2; ms++)
        #pragma unroll
        for (int ns = 0; ns < 4; ns++) {
            const int row = rowBlock + wm * 32 + ms * 16 + gid;
            const int col = colBlock + wn * 32 + ns * 8 + tig * 2;
            float2 bz = *(const float2*)(bias + col);
            float* a = acc[ms][ns];
            float f0 = a[0] + bz.x, f1 = a[1] + bz.y;
            float f2 = a[2] + bz.x, f3 = a[3] + bz.y;
            if (F32OUT) {
                *(float2*)(Cf + (long long)row * N + col)       = make_float2(f0, f1);
                *(float2*)(Cf + (long long)(row + 8) * N + col) = make_float2(f2, f3);
            } else {
                __nv_bfloat162 h, l;
                h.x = __float2bfloat16(f0); h.y = __float2bfloat16(f1);
                l.x = __float2bfloat16(f0 - __bfloat162float(h.x));
                l.y = __float2bfloat16(f1 - __bfloat162float(h.y));
                *(__nv_bfloat162*)(Chi + (long long)row * N + col) = h;
                *(__nv_bfloat162*)(Clo + (long long)row * N + col) = l;
                h.x = __float2bfloat16(f2); h.y = __float2bfloat16(f3);
                l.x = __float2bfloat16(f2 - __bfloat162float(h.x));
                l.y = __float2bfloat16(f3 - __bfloat162float(h.y));
                *(__nv_bfloat162*)(Chi + (long long)(row + 8) * N + col) = h;
                *(__nv_bfloat162*)(Clo + (long long)(row + 8) * N + col) = l;
            }
        }
}

// ---------------------------------------------------------------------------
// FUSED attention — re-tiled: 256 threads, 16 q-rows per block, 2 blocks/SM.
// 8 warps, wn = warp (8 x 16 cols per 128-wide ki tile). Per-thread work and
// MMA sequence identical to the 512-thread version (acc[8][2][4]).
// smem: Qhi|Qlo (16 rows) | 2x(Khi) | 2x(Klo) | redmax | redsum | Opart(32KB)
// total 112128 B -> 2 blocks/SM; regs 256x128 = half RF.
// ---------------------------------------------------------------------------
#define SC_QBUF (16 * QKP * 2)            // 2304
#define SC_KBUF (128 * QKP * 2)           // 18432 per buffer
#define SC_OQHI 0
#define SC_OQLO SC_QBUF
#define SC_OKHI (2 * SC_QBUF)             // 4608
#define SC_OKLO (SC_OKHI + 2 * SC_KBUF)   // 41472
#define SC_ORMAX (SC_OKLO + 2 * SC_KBUF)  // 78336
#define SC_ORSUM (SC_ORMAX + 512)         // 78848
#define SC_OPART (SC_ORSUM + 512)         // 79360 (8 warps x 16x64 f32 = 32KB)
#define SC_SMEM  (SC_OPART + 8 * 16 * 64 * 4)   // 112128

__global__ __launch_bounds__(256, 2) void fused_attn(
    const __nv_bfloat16* __restrict__ qh_hi, const __nv_bfloat16* __restrict__ qh_lo,
    const __nv_bfloat16* __restrict__ kh_hi, const __nv_bfloat16* __restrict__ kh_lo,
    const __nv_bfloat16* __restrict__ vh_hi, const __nv_bfloat16* __restrict__ vh_lo,
    float* __restrict__ attn,
    __nv_bfloat16* __restrict__ ctx_hi, __nv_bfloat16* __restrict__ ctx_lo)
{
    extern __shared__ __align__(16) char dynsmem[];
    const uint32_t sBase = smem_u32(dynsmem);
    const uint32_t sQhi = sBase + SC_OQHI;
    const uint32_t sQlo = sBase + SC_OQLO;
    const uint32_t sKhi = sBase + SC_OKHI;   // aliased by V in PV phase
    const uint32_t sKlo = sBase + SC_OKLO;
    float* redmax = (float*)(dynsmem + SC_ORMAX);   // [16][8]
    float* redsum = (float*)(dynsmem + SC_ORSUM);   // [16][8]
    float* Opart  = (float*)(dynsmem + SC_OPART);   // [8][16][64]

    const int tid = threadIdx.x;
    const int warp = tid >> 5, lane = tid & 31;
    const int wn = warp;                          // 0..7
    const int qiBlock = blockIdx.x * 16;
    const int bh = blockIdx.y;                    // h*8 + b
    const int b = bh & 7, h = bh >> 3;

    const long long base  = (long long)b * SEQ * DMODEL + h * DK;
    const long long obase = (long long)bh * SEQ * SEQ;

    // Q load (once): 16 rows x 64 bf16 per array = 128 chunks of 16B
    {
        const int chunk = tid & 127;
        const int qr = chunk >> 3, qs = chunk & 7;
        const uint32_t dst = (tid < 128 ? sQhi : sQlo) + (uint32_t)(qr * QKP + qs * 8) * 2;
        const __nv_bfloat16* src = (tid < 128 ? qh_hi : qh_lo) +
            base + (long long)(qiBlock + qr) * DMODEL + qs * 8;
        CPA16(dst, src);
    }

    // K/V tiles: 128 rows x 8 segs = 1024 chunks per array; 4 per thread each
    auto load_k = [&](int kt, int buf) {
        #pragma unroll
        for (int p = 0; p < 4; p++) {
            const int chunk = tid + p * 256;
            const int kr = chunk >> 3, ks = chunk & 7;
            const long long g = base + (long long)(kt * 128 + kr) * DMODEL + ks * 8;
            const uint32_t so = (uint32_t)(kr * QKP + ks * 8) * 2;
            CPA16(sKhi + buf * SC_KBUF + so, kh_hi + g);
            CPA16(sKlo + buf * SC_KBUF + so, kh_lo + g);
        }
        CPA_COMMIT();
    };
    auto load_v = [&](int kt, int buf) {
        #pragma unroll
        for (int p = 0; p < 4; p++) {
            const int chunk = tid + p * 256;
            const int kr = chunk >> 3, ks = chunk & 7;
            const long long g = base + (long long)(kt * 128 + kr) * DMODEL + ks * 8;
            const uint32_t so = (uint32_t)(kr * QKP + ks * 8) * 2;
            CPA16(sKhi + buf * SC_KBUF + so, vh_hi + g);
            CPA16(sKlo + buf * SC_KBUF + so, vh_lo + g);
        }
        CPA_COMMIT();
    };

    float acc[8][2][4];
    #pragma unroll
    for (int t = 0; t < 8; t++)
        #pragma unroll
        for (int n = 0; n < 2; n++)
            #pragma unroll
            for (int i = 0; i < 4; i++) acc[t][n][i] = 0.f;

    const int alr = (lane & 7) + ((lane >> 3) & 1) * 8;
    const int alc = (lane >> 4) * 8;
    const int bnr = (lane & 7) + ((lane >> 4) & 1) * 8;
    const int bkc = ((lane >> 3) & 1) * 8;
    const int vkr = (lane & 7) + ((lane >> 3) & 1) * 8;   // trans row (ki)
    const int vnc = ((lane >> 4) & 1) * 8;                // trans col (d)

    // ---------------- S = Q K^T phase ----------------
    load_k(0, 0);
    #pragma unroll
    for (int kt = 0; kt < 8; kt++) {
        const int buf = kt & 1;
        if (kt < 7) { load_k(kt + 1, (kt + 1) & 1); CPA_WAIT1(); }
        else        { CPA_WAIT0(); }
        __syncthreads();

        const uint32_t kh_b = sKhi + buf * SC_KBUF;
        const uint32_t kl_b = sKlo + buf * SC_KBUF;
        #pragma unroll
        for (int kk = 0; kk < 64; kk += 16) {
            uint32_t ahi[4], alo[4];
            {
                uint32_t off = (uint32_t)(alr * QKP + kk + alc) * 2;
                LDMX4(ahi[0], ahi[1], ahi[2], ahi[3], sQhi + off);
                LDMX4(alo[0], alo[1], alo[2], alo[3], sQlo + off);
            }
            uint32_t bhi[2][2], blo[2][2];
            {
                uint32_t off = (uint32_t)((wn * 16 + bnr) * QKP + kk + bkc) * 2;
                uint32_t r0, r1, r2, r3;
                LDMX4(r0, r1, r2, r3, kh_b + off);
                bhi[0][0] = r0; bhi[0][1] = r1; bhi[1][0] = r2; bhi[1][1] = r3;
                LDMX4(r0, r1, r2, r3, kl_b + off);
                blo[0][0] = r0; blo[0][1] = r1; blo[1][0] = r2; blo[1][1] = r3;
            }
            #pragma unroll
            for (int nf = 0; nf < 2; nf++) {
                MMA16816(acc[kt][nf], ahi, bhi[nf]);
                MMA16816(acc[kt][nf], alo, bhi[nf]);
                MMA16816(acc[kt][nf], ahi, blo[nf]);
            }
        }
        __syncthreads();
    }

    // ---------------- softmax ----------------
    const int gid = lane >> 2, tig = lane & 3;
    const int r0 = gid;           // local row of c0,c1
    const int r1 = r0 + 8;        // local row of c2,c3
    const float scale = 0.125f;

    float m0 = -1e30f, m1 = -1e30f;
    #pragma unroll
    for (int t = 0; t < 8; t++)
        #pragma unroll
        for (int n = 0; n < 2; n++) {
            m0 = fmaxf(m0, fmaxf(acc[t][n][0], acc[t][n][1]));
            m1 = fmaxf(m1, fmaxf(acc[t][n][2], acc[t][n][3]));
        }
    #pragma unroll
    for (int o = 1; o <= 2; o <<= 1) {
        m0 = fmaxf(m0, __shfl_xor_sync(0xffffffffu, m0, o));
        m1 = fmaxf(m1, __shfl_xor_sync(0xffffffffu, m1, o));
    }
    if (tig == 0) { redmax[r0 * 8 + wn] = m0; redmax[r1 * 8 + wn] = m1; }
    __syncthreads();
    float rm0 = redmax[r0 * 8], rm1 = redmax[r1 * 8];
    #pragma unroll
    for (int w = 1; w < 8; w++) {
        rm0 = fmaxf(rm0, redmax[r0 * 8 + w]);
        rm1 = fmaxf(rm1, redmax[r1 * 8 + w]);
    }

    float s0 = 0.f, s1 = 0.f;
    #pragma unroll
    for (int t = 0; t < 8; t++)
        #pragma unroll
        for (int n = 0; n < 2; n++) {
            float e0 = __expf((acc[t][n][0] - rm0) * scale);
            float e1 = __expf((acc[t][n][1] - rm0) * scale);
            float e2 = __expf((acc[t][n][2] - rm1) * scale);
            float e3 = __expf((acc[t][n][3] - rm1) * scale);
            acc[t][n][0] = e0; acc[t][n][1] = e1;
            acc[t][n][2] = e2; acc[t][n][3] = e3;
            s0 += e0 + e1;
            s1 += e2 + e3;
        }
    #pragma unroll
    for (int o = 1; o <= 2; o <<= 1) {
        s0 += __shfl_xor_sync(0xffffffffu, s0, o);
        s1 += __shfl_xor_sync(0xffffffffu, s1, o);
    }
    if (tig == 0) { redsum[r0 * 8 + wn] = s0; redsum[r1 * 8 + wn] = s1; }
    __syncthreads();
    float t0 = 0.f, t1 = 0.f;
    #pragma unroll
    for (int w = 0; w < 8; w++) { t0 += redsum[r0 * 8 + w]; t1 += redsum[r1 * 8 + w]; }
    const float inv0 = __fdividef(1.f, t0);
    const float inv1 = __fdividef(1.f, t1);

    // ---------------- P @ V phase (V streamed into dead K buffers) --------
    const long long row0 = obase + (long long)(qiBlock + r0) * SEQ;
    const long long row1 = obase + (long long)(qiBlock + r1) * SEQ;

    float accO[8][4];
    #pragma unroll
    for (int nf = 0; nf < 8; nf++)
        #pragma unroll
        for (int i = 0; i < 4; i++) accO[nf][i] = 0.f;

    load_v(0, 0);
    #pragma unroll
    for (int t = 0; t < 8; t++) {
        const int buf = t & 1;
        if (t < 7) { load_v(t + 1, (t + 1) & 1); CPA_WAIT1(); }
        else       { CPA_WAIT0(); }

        // normalize P, store attn output, build A-frags (hi/lo)
        float p00 = acc[t][0][0] * inv0, p01 = acc[t][0][1] * inv0;
        float p02 = acc[t][0][2] * inv1, p03 = acc[t][0][3] * inv1;
        float p10 = acc[t][1][0] * inv0, p11 = acc[t][1][1] * inv0;
        float p12 = acc[t][1][2] * inv1, p13 = acc[t][1][3] * inv1;
        {
            const int col = t * 128 + wn * 16 + tig * 2;
            *(float2*)(attn + row0 + col)     = make_float2(p00, p01);
            *(float2*)(attn + row1 + col)     = make_float2(p02, p03);
            *(float2*)(attn + row0 + col + 8) = make_float2(p10, p11);
            *(float2*)(attn + row1 + col + 8) = make_float2(p12, p13);
        }
        uint32_t aPh[4], aPl[4];
        aPh[0] = pack_hi(p00, p01); aPl[0] = pack_lo(p00, p01);
        aPh[1] = pack_hi(p02, p03); aPl[1] = pack_lo(p02, p03);
        aPh[2] = pack_hi(p10, p11); aPl[2] = pack_lo(p10, p11);
        aPh[3] = pack_hi(p12, p13); aPl[3] = pack_lo(p12, p13);

        __syncthreads();   // V tile ready, previous tile reads done

        const uint32_t vh_b = sKhi + buf * SC_KBUF;
        const uint32_t vl_b = sKlo + buf * SC_KBUF;
        #pragma unroll
        for (int nb = 0; nb < 4; nb++) {
            uint32_t off = (uint32_t)((wn * 16 + vkr) * QKP + nb * 16 + vnc) * 2;
            uint32_t bhiV[2][2], bloV[2][2];
            uint32_t r0v, r1v, r2v, r3v;
            LDMX4T(r0v, r1v, r2v, r3v, vh_b + off);
            bhiV[0][0] = r0v; bhiV[0][1] = r1v; bhiV[1][0] = r2v; bhiV[1][1] = r3v;
            LDMX4T(r0v, r1v, r2v, r3v, vl_b + off);
            bloV[0][0] = r0v; bloV[0][1] = r1v; bloV[1][0] = r2v; bloV[1][1] = r3v;
            #pragma unroll
            for (int j = 0; j < 2; j++) {
                const int nf = nb * 2 + j;
                MMA16816(accO[nf], aPh, bhiV[j]);
                MMA16816(accO[nf], aPl, bhiV[j]);
                MMA16816(accO[nf], aPh, bloV[j]);
            }
        }
        __syncthreads();
    }

    // ---------------- cross-warp O reduction + ctx store ----------------
    {
        float* mine = Opart + wn * (16 * 64);
        #pragma unroll
        for (int nf = 0; nf < 8; nf++) {
            const int col = nf * 8 + tig * 2;
            *(float2*)(mine + gid * 64 + col)       = make_float2(accO[nf][0], accO[nf][1]);
            *(float2*)(mine + (gid + 8) * 64 + col) = make_float2(accO[nf][2], accO[nf][3]);
        }
    }
    __syncthreads();
    {
        const int e = tid * 4;
        const int row = e >> 6;          // 0..15
        const int col = e & 63;
        float4 s = make_float4(0.f, 0.f, 0.f, 0.f);
        #pragma unroll
        for (int w = 0; w < 8; w++) {
            float4 v = *(float4*)(Opart + w * (16 * 64) + row * 64 + col);
            s.x += v.x; s.y += v.y; s.z += v.z; s.w += v.w;
        }
        const long long dst = base + (long long)(qiBlock + row) * DMODEL + col;
        __nv_bfloat162 h0, h1, l0, l1;
        h0.x = __float2bfloat16(s.x); h0.y = __float2bfloat16(s.y);
        l0.x = __float2bfloat16(s.x - __bfloat162float(h0.x));
        l0.y = __float2bfloat16(s.y - __bfloat162float(h0.y));
        h1.x = __float2bfloat16(s.z); h1.y = __float2bfloat16(s.w);
        l1.x = __float2bfloat16(s.z - __bfloat162float(h1.x));
        l1.y = __float2bfloat16(s.w - __bfloat162float(h1.y));
        *(__nv_bfloat162*)(ctx_hi + dst)     = h0;
        *(__nv_bfloat162*)(ctx_hi + dst + 2) = h1;
        *(__nv_bfloat162*)(ctx_lo + dst)     = l0;
        *(__nv_bfloat162*)(ctx_lo + dst + 2) = l1;
    }
}

// ---------------------------------------------------------------------------
// Launcher
// ---------------------------------------------------------------------------
extern "C" void kernel_launch(void* const* d_in, const int* in_sizes, int n_in,
                              void* d_out, int out_size)
{
    (void)in_sizes; (void)n_in; (void)out_size;

    const float* q   = (const float*)d_in[0];
    const float* k   = (const float*)d_in[1];
    const float* v   = (const float*)d_in[2];
    const float* Wq  = (const float*)d_in[3];
    const float* bq  = (const float*)d_in[4];
    const float* Wk  = (const float*)d_in[5];
    const float* bk  = (const float*)d_in[6];
    const float* Wv  = (const float*)d_in[7];
    const float* bv  = (const float*)d_in[8];
    const float* Wfc = (const float*)d_in[9];
    const float* bfc = (const float*)d_in[10];

    float* out  = (float*)d_out;
    float* attn = out + OUT_ELEMS;

    __nv_bfloat16 *q_hi, *q_lo, *k_hi, *k_lo, *v_hi, *v_lo;
    __nv_bfloat16 *Wq_hi, *Wq_lo, *Wk_hi, *Wk_lo, *Wv_hi, *Wv_lo, *Wfc_hi, *Wfc_lo;
    __nv_bfloat16 *qh_hi, *qh_lo, *kh_hi, *kh_lo, *vh_hi, *vh_lo, *ctx_hi, *ctx_lo;
    cudaGetSymbolAddress((void**)&q_hi, g_q_hi);   cudaGetSymbolAddress((void**)&q_lo, g_q_lo);
    cudaGetSymbolAddress((void**)&k_hi, g_k_hi);   cudaGetSymbolAddress((void**)&k_lo, g_k_lo);
    cudaGetSymbolAddress((void**)&v_hi, g_v_hi);   cudaGetSymbolAddress((void**)&v_lo, g_v_lo);
    cudaGetSymbolAddress((void**)&Wq_hi, g_Wq_hi); cudaGetSymbolAddress((void**)&Wq_lo, g_Wq_lo);
    cudaGetSymbolAddress((void**)&Wk_hi, g_Wk_hi); cudaGetSymbolAddress((void**)&Wk_lo, g_Wk_lo);
    cudaGetSymbolAddress((void**)&Wv_hi, g_Wv_hi); cudaGetSymbolAddress((void**)&Wv_lo, g_Wv_lo);
    cudaGetSymbolAddress((void**)&Wfc_hi, g_Wfc_hi); cudaGetSymbolAddress((void**)&Wfc_lo, g_Wfc_lo);
    cudaGetSymbolAddress((void**)&qh_hi, g_qh_hi); cudaGetSymbolAddress((void**)&qh_lo, g_qh_lo);
    cudaGetSymbolAddress((void**)&kh_hi, g_kh_hi); cudaGetSymbolAddress((void**)&kh_lo, g_kh_lo);
    cudaGetSymbolAddress((void**)&vh_hi, g_vh_hi); cudaGetSymbolAddress((void**)&vh_lo, g_vh_lo);
    cudaGetSymbolAddress((void**)&ctx_hi, g_ctx_hi); cudaGetSymbolAddress((void**)&ctx_lo, g_ctx_lo);

    cudaFuncSetAttribute(proj_gemm_async<false>,
                         cudaFuncAttributeMaxDynamicSharedMemorySize, PRJ_SMEM);
    cudaFuncSetAttribute(proj_gemm_async<true>,
                         cudaFuncAttributeMaxDynamicSharedMemorySize, PRJ_SMEM);
    cudaFuncSetAttribute(fused_attn,
                         cudaFuncAttributeMaxDynamicSharedMemorySize, SC_SMEM);

    const int nBig = MROWS * DMODEL;
    const int nW   = DMODEL * DMODEL;
    split_kernel<<<nBig / 1024, 256>>>(q, q_hi, q_lo);
    split_kernel<<<nBig / 1024, 256>>>(k, k_hi, k_lo);
    split_kernel<<<nBig / 1024, 256>>>(v, v_hi, v_lo);
    split_kernel<<<nW / 1024, 256>>>(Wq,  Wq_hi,  Wq_lo);
    split_kernel<<<nW / 1024, 256>>>(Wk,  Wk_hi,  Wk_lo);
    split_kernel<<<nW / 1024, 256>>>(Wv,  Wv_hi,  Wv_lo);
    split_kernel<<<nW / 1024, 256>>>(Wfc, Wfc_hi, Wfc_lo);

    dim3 gProj(DMODEL / 128, MROWS / 64);            // (8, 128)
    proj_gemm_async<false><<<gProj, 256, PRJ_SMEM>>>(
        q_hi, q_lo, Wq_hi, Wq_lo, bq, nullptr, qh_hi, qh_lo, MROWS, DMODEL, DMODEL);
    proj_gemm_async<false><<<gProj, 256, PRJ_SMEM>>>(
        k_hi, k_lo, Wk_hi, Wk_lo, bk, nullptr, kh_hi, kh_lo, MROWS, DMODEL, DMODEL);
    proj_gemm_async<false><<<gProj, 256, PRJ_SMEM>>>(
        v_hi, v_lo, Wv_hi, Wv_lo, bv, nullptr, vh_hi, vh_lo, MROWS, DMODEL, DMODEL);

    dim3 gAttn(SEQ / 16, BATCH * NHEAD);             // (64, 128)
    fused_attn<<<gAttn, 256, SC_SMEM>>>(qh_hi, qh_lo, kh_hi, kh_lo,
                                        vh_hi, vh_lo, attn, ctx_hi, ctx_lo);

    proj_gemm_async<true><<<gProj, 256, PRJ_SMEM>>>(
        ctx_hi, ctx_lo, Wfc_hi, Wfc_lo, bfc, out, nullptr, nullptr, MROWS, DMODEL, DMODEL);
}

// round 14
// speedup vs baseline: 1.2389x; 1.2389x over previous
#include <cuda_runtime.h>
#include <cuda_fp16.h>
#include <math.h>
#include <stdint.h>

// ---------------------------------------------------------------------------
// MultiHeadAttention: B=8, L=1024, D_MODEL=1024, H=16, Dk=64
// Round 13: round-11 structure (proj 256t/2SM, attn 512t round-5 shape) with
// fp16 arithmetic: proj = A(hi+lo fp16) x B(single fp16) -> 2 MMAs/k-step;
// attn = 3-term fp16 hi/lo (precision better than old bf16x3).
// d_out = [ out (8*1024*1024 f32) | attn_flat ((16*8)*1024*1024 f32) ]
// ---------------------------------------------------------------------------

#define BATCH 8
#define SEQ   1024
#define DMODEL 1024
#define NHEAD 16
#define DK    64
#define MROWS (BATCH * SEQ)          // 8192
#define OUT_ELEMS (MROWS * DMODEL)   // 8388608

#define BKP  40    // 32 + 8 pad (fp16) A tiles (proj)
#define BNP  136   // 128 + 8 pad  B tiles (proj)
#define QKP  72    // 64 + 8 pad   attn Q/K/V tiles

// ---------------- static scratch (no allocations) ----------------
__device__ __half g_q_hi[MROWS * DMODEL],  g_q_lo[MROWS * DMODEL];
__device__ __half g_k_hi[MROWS * DMODEL],  g_k_lo[MROWS * DMODEL];
__device__ __half g_v_hi[MROWS * DMODEL],  g_v_lo[MROWS * DMODEL];
__device__ __half g_Wq[DMODEL * DMODEL];
__device__ __half g_Wk[DMODEL * DMODEL];
__device__ __half g_Wv[DMODEL * DMODEL];
__device__ __half g_Wfc[DMODEL * DMODEL];
__device__ __half g_qh_hi[MROWS * DMODEL], g_qh_lo[MROWS * DMODEL];
__device__ __half g_kh_hi[MROWS * DMODEL], g_kh_lo[MROWS * DMODEL];
__device__ __half g_vh_hi[MROWS * DMODEL], g_vh_lo[MROWS * DMODEL];
__device__ __half g_ctx_hi[MROWS * DMODEL], g_ctx_lo[MROWS * DMODEL];

// ---------------------------------------------------------------------------
// PTX helpers
// ---------------------------------------------------------------------------
__device__ __forceinline__ uint32_t smem_u32(const void* p) {
    return (uint32_t)__cvta_generic_to_shared(p);
}

#define LDMX4(r0,r1,r2,r3,addr) \
    asm volatile("ldmatrix.sync.aligned.m8n8.x4.shared.b16 {%0,%1,%2,%3}, [%4];" \
        : "=r"(r0), "=r"(r1), "=r"(r2), "=r"(r3) : "r"(addr))

#define LDMX4T(r0,r1,r2,r3,addr) \
    asm volatile("ldmatrix.sync.aligned.m8n8.x4.trans.shared.b16 {%0,%1,%2,%3}, [%4];" \
        : "=r"(r0), "=r"(r1), "=r"(r2), "=r"(r3) : "r"(addr))

#define MMA16816(c, a, b) \
    asm volatile("mma.sync.aligned.m16n8k16.row.col.f32.f16.f16.f32 " \
        "{%0,%1,%2,%3}, {%4,%5,%6,%7}, {%8,%9}, {%0,%1,%2,%3};" \
        : "+f"((c)[0]), "+f"((c)[1]), "+f"((c)[2]), "+f"((c)[3]) \
        : "r"((a)[0]), "r"((a)[1]), "r"((a)[2]), "r"((a)[3]), \
          "r"((b)[0]), "r"((b)[1]))

#define CPA16(dst, src) \
    asm volatile("cp.async.cg.shared.global [%0], [%1], 16;" :: "r"(dst), "l"(src))
#define CPA_COMMIT() asm volatile("cp.async.commit_group;")
#define CPA_WAIT1()  asm volatile("cp.async.wait_group 1;")
#define CPA_WAIT0()  asm volatile("cp.async.wait_group 0;")

__device__ __forceinline__ uint32_t pack_hi(float x, float y) {
    __half2 h;
    h.x = __float2half(x); h.y = __float2half(y);
    return *(uint32_t*)&h;
}
__device__ __forceinline__ uint32_t pack_lo(float x, float y) {
    __half hx = __float2half(x), hy = __float2half(y);
    __half2 l;
    l.x = __float2half(x - __half2float(hx));
    l.y = __float2half(y - __half2float(hy));
    return *(uint32_t*)&l;
}

// ---------------------------------------------------------------------------
// Elementwise pre-split: f32 -> (hi, lo) fp16
// ---------------------------------------------------------------------------
__global__ __launch_bounds__(256) void split_kernel(
    const float* __restrict__ in, __half* __restrict__ hi,
    __half* __restrict__ lo)
{
    const int i = (blockIdx.x * 256 + threadIdx.x) * 4;
    float4 v = *(const float4*)(in + i);
    __half h0 = __float2half(v.x);
    __half h1 = __float2half(v.y);
    __half h2 = __float2half(v.z);
    __half h3 = __float2half(v.w);
    __half2 hp0; hp0.x = h0; hp0.y = h1;
    __half2 hp1; hp1.x = h2; hp1.y = h3;
    *(__half2*)(hi + i)     = hp0;
    *(__half2*)(hi + i + 2) = hp1;
    __half2 lp0, lp1;
    lp0.x = __float2half(v.x - __half2float(h0));
    lp0.y = __float2half(v.y - __half2float(h1));
    lp1.x = __float2half(v.z - __half2float(h2));
    lp1.y = __float2half(v.w - __half2float(h3));
    *(__half2*)(lo + i)     = lp0;
    *(__half2*)(lo + i + 2) = lp1;
}

// Single fp16 convert (weights)
__global__ __launch_bounds__(256) void convert_kernel(
    const float* __restrict__ in, __half* __restrict__ outp)
{
    const int i = (blockIdx.x * 256 + threadIdx.x) * 4;
    float4 v = *(const float4*)(in + i);
    __half2 p0, p1;
    p0.x = __float2half(v.x); p0.y = __float2half(v.y);
    p1.x = __float2half(v.z); p1.y = __float2half(v.w);
    *(__half2*)(outp + i)     = p0;
    *(__half2*)(outp + i + 2) = p1;
}

// ---------------------------------------------------------------------------
// Projection GEMM — 256 threads, 64x128 tile, BK=32, 2-stage cp.async,
// 2 blocks/SM. A = (hi+lo) fp16 split, B = single fp16 -> 2 MMAs/k-step.
// smem: Ahi[2][64][40] | Alo | Bh[2][32][136]  = 37888 B
// ---------------------------------------------------------------------------
#define PRJ_ABUF (64 * BKP * 2)            // 5120
#define PRJ_BBUF (32 * BNP * 2)            // 8704
#define PRJ_OAHI 0
#define PRJ_OALO (2 * PRJ_ABUF)            // 10240
#define PRJ_OB   (4 * PRJ_ABUF)            // 20480
#define PRJ_SMEM (PRJ_OB + 2 * PRJ_BBUF)   // 37888

template<bool F32OUT>
__global__ __launch_bounds__(256, 2) void proj_gemm_async(
    const __half* __restrict__ Ahi_g, const __half* __restrict__ Alo_g,
    const __half* __restrict__ B_g,
    const float* __restrict__ bias,
    float* __restrict__ Cf, __half* __restrict__ Chi, __half* __restrict__ Clo,
    int M, int N, int K)
{
    extern __shared__ __align__(16) char dynsmem[];
    const uint32_t sBase = smem_u32(dynsmem);
    const uint32_t sAhi = sBase + PRJ_OAHI;
    const uint32_t sAlo = sBase + PRJ_OALO;
    const uint32_t sB   = sBase + PRJ_OB;

    const int tid = threadIdx.x;
    const int warp = tid >> 5, lane = tid & 31;
    const int wm = warp & 1, wn = warp >> 1;       // 2 x 4
    const int rowBlock = blockIdx.y * 64;
    const int colBlock = blockIdx.x * 128;

    const int arow = tid >> 2, aseg = tid & 3;
    const long long aGbase = (long long)(rowBlock + arow) * K + aseg * 8;
    const uint32_t aSoff = (uint32_t)(arow * BKP + aseg * 8) * 2;
    const int brow0 = tid >> 4,          bseg0 = tid & 15;
    const int brow1 = (tid + 256) >> 4,  bseg1 = (tid + 256) & 15;
    const long long bGbase0 = (long long)brow0 * N + colBlock + bseg0 * 8;
    const long long bGbase1 = (long long)brow1 * N + colBlock + bseg1 * 8;
    const uint32_t bSoff0 = (uint32_t)(brow0 * BNP + bseg0 * 8) * 2;
    const uint32_t bSoff1 = (uint32_t)(brow1 * BNP + bseg1 * 8) * 2;

    auto load_tile = [&](int kt, int buf) {
        const long long ka  = aGbase + kt * 32;
        const long long kb0 = bGbase0 + (long long)(kt * 32) * N;
        const long long kb1 = bGbase1 + (long long)(kt * 32) * N;
        CPA16(sAhi + buf * PRJ_ABUF + aSoff, Ahi_g + ka);
        CPA16(sAlo + buf * PRJ_ABUF + aSoff, Alo_g + ka);
        CPA16(sB + buf * PRJ_BBUF + bSoff0, B_g + kb0);
        CPA16(sB + buf * PRJ_BBUF + bSoff1, B_g + kb1);
        CPA_COMMIT();
    };

    float acc[2][4][4];
    #pragma unroll
    for (int i = 0; i < 2; i++)
        #pragma unroll
        for (int j = 0; j < 4; j++)
            #pragma unroll
            for (int l = 0; l < 4; l++) acc[i][j][l] = 0.f;

    const int alr = (lane & 7) + ((lane >> 3) & 1) * 8;
    const int alc = (lane >> 4) * 8;
    const int bkr = (lane & 7) + ((lane >> 3) & 1) * 8;
    const int bnc = ((lane >> 4) & 1) * 8;

    const int KT = K / 32;
    load_tile(0, 0);
    for (int kt = 0; kt < KT; kt++) {
        const int buf = kt & 1;
        if (kt + 1 < KT) { load_tile(kt + 1, (kt + 1) & 1); CPA_WAIT1(); }
        else             { CPA_WAIT0(); }
        __syncthreads();

        const uint32_t bAhi = sAhi + buf * PRJ_ABUF;
        const uint32_t bAlo = sAlo + buf * PRJ_ABUF;
        const uint32_t bB   = sB + buf * PRJ_BBUF;

        #pragma unroll
        for (int kk = 0; kk < 32; kk += 16) {
            uint32_t ahi[2][4], alo[2][4];
            #pragma unroll
            for (int ms = 0; ms < 2; ms++) {
                uint32_t off = (uint32_t)((wm * 32 + ms * 16 + alr) * BKP + kk + alc) * 2;
                LDMX4(ahi[ms][0], ahi[ms][1], ahi[ms][2], ahi[ms][3], bAhi + off);
                LDMX4(alo[ms][0], alo[ms][1], alo[ms][2], alo[ms][3], bAlo + off);
            }
            uint32_t bfr[4][2];
            #pragma unroll
            for (int np = 0; np < 2; np++) {
                uint32_t r0, r1, r2, r3;
                uint32_t off = (uint32_t)((kk + bkr) * BNP + wn * 32 + np * 16 + bnc) * 2;
                LDMX4T(r0, r1, r2, r3, bB + off);
                bfr[np*2][0] = r0; bfr[np*2][1] = r1;
                bfr[np*2+1][0] = r2; bfr[np*2+1][1] = r3;
            }
            #pragma unroll
            for (int ms = 0; ms < 2; ms++)
                #pragma unroll
                for (int ns = 0; ns < 4; ns++) {
                    MMA16816(acc[ms][ns], ahi[ms], bfr[ns]);
                    MMA16816(acc[ms][ns], alo[ms], bfr[ns]);
                }
        }
        __syncthreads();
    }

    const int gid = lane >> 2, tig = lane & 3;
    #pragma unroll
    for (int ms = 0; ms < 2; ms++)
        #pragma unroll
        for (int ns = 0; ns < 4; ns++) {
            const int row = rowBlock + wm * 32 + ms * 16 + gid;
            const int col = colBlock + wn * 32 + ns * 8 + tig * 2;
            float2 bz = *(const float2*)(bias + col);
            float* a = acc[ms][ns];
            float f0 = a[0] + bz.x, f1 = a[1] + bz.y;
            float f2 = a[2] + bz.x, f3 = a[3] + bz.y;
            if (F32OUT) {
                *(float2*)(Cf + (long long)row * N + col)       = make_float2(f0, f1);
                *(float2*)(Cf + (long long)(row + 8) * N + col) = make_float2(f2, f3);
            } else {
                __half2 h, l;
                h.x = __float2half(f0); h.y = __float2half(f1);
                l.x = __float2half(f0 - __half2float(h.x));
                l.y = __float2half(f1 - __half2float(h.y));
                *(__half2*)(Chi + (long long)row * N + col) = h;
                *(__half2*)(Clo + (long long)row * N + col) = l;
                h.x = __float2half(f2); h.y = __float2half(f3);
                l.x = __float2half(f2 - __half2float(h.x));
                l.y = __float2half(f3 - __half2float(h.y));
                *(__half2*)(Chi + (long long)(row + 8) * N + col) = h;
                *(__half2*)(Clo + (long long)(row + 8) * N + col) = l;
            }
        }
}

// ---------------------------------------------------------------------------
// FUSED attention — round-11 512-thread structure, fp16 hi/lo operands,
// 3-term MMA (precision ~2^-22, better than the old bf16x3).
// ---------------------------------------------------------------------------
#define SC_QBUF (32 * QKP * 2)            // 4608
#define SC_KBUF (128 * QKP * 2)           // 18432 per buffer
#define SC_OQHI 0
#define SC_OQLO SC_QBUF
#define SC_OKHI (2 * SC_QBUF)             // 9216
#define SC_OKLO (SC_OKHI + 2 * SC_KBUF)   // 46080
#define SC_ORMAX (SC_OKLO + 2 * SC_KBUF)  // 82944
#define SC_ORSUM (SC_ORMAX + 1024)        // 83968
#define SC_OPART (SC_ORSUM + 1024)        // 84992
#define SC_SMEM  (SC_OPART + 16 * 16 * 64 * 4)   // 150528

__global__ __launch_bounds__(512, 1) void fused_attn(
    const __half* __restrict__ qh_hi, const __half* __restrict__ qh_lo,
    const __half* __restrict__ kh_hi, const __half* __restrict__ kh_lo,
    const __half* __restrict__ vh_hi, const __half* __restrict__ vh_lo,
    float* __restrict__ attn,
    __half* __restrict__ ctx_hi, __half* __restrict__ ctx_lo)
{
    extern __shared__ __align__(16) char dynsmem[];
    const uint32_t sBase = smem_u32(dynsmem);
    const uint32_t sQhi = sBase + SC_OQHI;
    const uint32_t sQlo = sBase + SC_OQLO;
    const uint32_t sKhi = sBase + SC_OKHI;   // aliased by V in PV phase
    const uint32_t sKlo = sBase + SC_OKLO;
    float* redmax = (float*)(dynsmem + SC_ORMAX);
    float* redsum = (float*)(dynsmem + SC_ORSUM);
    float* Opart  = (float*)(dynsmem + SC_OPART);

    const int tid = threadIdx.x;
    const int warp = tid >> 5, lane = tid & 31;
    const int wm = warp & 1, wn = warp >> 1;
    const int qiBlock = blockIdx.x * 32;
    const int bh = blockIdx.y;                    // h*8 + b
    const int b = bh & 7, h = bh >> 3;

    const long long base  = (long long)b * SEQ * DMODEL + h * DK;
    const long long obase = (long long)bh * SEQ * SEQ;

    // Q load (once)
    {
        const int chunk = tid & 255;
        const int qr = chunk >> 3, qs = chunk & 7;
        const uint32_t dst = (tid < 256 ? sQhi : sQlo) + (uint32_t)(qr * QKP + qs * 8) * 2;
        const __half* src = (tid < 256 ? qh_hi : qh_lo) +
            base + (long long)(qiBlock + qr) * DMODEL + qs * 8;
        CPA16(dst, src);
    }

    auto load_k = [&](int kt, int buf) {
        #pragma unroll
        for (int p = 0; p < 2; p++) {
            const int chunk = tid + p * 512;
            const int kr = chunk >> 3, ks = chunk & 7;
            const long long g = base + (long long)(kt * 128 + kr) * DMODEL + ks * 8;
            const uint32_t so = (uint32_t)(kr * QKP + ks * 8) * 2;
            CPA16(sKhi + buf * SC_KBUF + so, kh_hi + g);
            CPA16(sKlo + buf * SC_KBUF + so, kh_lo + g);
        }
        CPA_COMMIT();
    };
    auto load_v = [&](int kt, int buf) {
        #pragma unroll
        for (int p = 0; p < 2; p++) {
            const int chunk = tid + p * 512;
            const int kr = chunk >> 3, ks = chunk & 7;
            const long long g = base + (long long)(kt * 128 + kr) * DMODEL + ks * 8;
            const uint32_t so = (uint32_t)(kr * QKP + ks * 8) * 2;
            CPA16(sKhi + buf * SC_KBUF + so, vh_hi + g);
            CPA16(sKlo + buf * SC_KBUF + so, vh_lo + g);
        }
        CPA_COMMIT();
    };

    float acc[8][2][4];
    #pragma unroll
    for (int t = 0; t < 8; t++)
        #pragma unroll
        for (int n = 0; n < 2; n++)
            #pragma unroll
            for (int i = 0; i < 4; i++) acc[t][n][i] = 0.f;

    const int alr = (lane & 7) + ((lane >> 3) & 1) * 8;
    const int alc = (lane >> 4) * 8;
    const int bnr = (lane & 7) + ((lane >> 4) & 1) * 8;
    const int bkc = ((lane >> 3) & 1) * 8;
    const int vkr = (lane & 7) + ((lane >> 3) & 1) * 8;   // trans row (ki)
    const int vnc = ((lane >> 4) & 1) * 8;                // trans col (d)

    // ---------------- S = Q K^T phase ----------------
    load_k(0, 0);
    #pragma unroll
    for (int kt = 0; kt < 8; kt++) {
        const int buf = kt & 1;
        if (kt < 7) { load_k(kt + 1, (kt + 1) & 1); CPA_WAIT1(); }
        else        { CPA_WAIT0(); }
        __syncthreads();

        const uint32_t kh_b = sKhi + buf * SC_KBUF;
        const uint32_t kl_b = sKlo + buf * SC_KBUF;
        #pragma unroll
        for (int kk = 0; kk < 64; kk += 16) {
            uint32_t ahi[4], alo[4];
            {
                uint32_t off = (uint32_t)((wm * 16 + alr) * QKP + kk + alc) * 2;
                LDMX4(ahi[0], ahi[1], ahi[2], ahi[3], sQhi + off);
                LDMX4(alo[0], alo[1], alo[2], alo[3], sQlo + off);
            }
            uint32_t bhi[2][2], blo[2][2];
            {
                uint32_t off = (uint32_t)((wn * 16 + bnr) * QKP + kk + bkc) * 2;
                uint32_t r0, r1, r2, r3;
                LDMX4(r0, r1, r2, r3, kh_b + off);
                bhi[0][0] = r0; bhi[0][1] = r1; bhi[1][0] = r2; bhi[1][1] = r3;
                LDMX4(r0, r1, r2, r3, kl_b + off);
                blo[0][0] = r0; blo[0][1] = r1; blo[1][0] = r2; blo[1][1] = r3;
            }
            #pragma unroll
            for (int nf = 0; nf < 2; nf++) {
                MMA16816(acc[kt][nf], ahi, bhi[nf]);
                MMA16816(acc[kt][nf], alo, bhi[nf]);
                MMA16816(acc[kt][nf], ahi, blo[nf]);
            }
        }
        __syncthreads();
    }

    // ---------------- softmax ----------------
    const int gid = lane >> 2, tig = lane & 3;
    const int r0 = wm * 16 + gid;
    const int r1 = r0 + 8;
    const float scale = 0.125f;

    float m0 = -1e30f, m1 = -1e30f;
    #pragma unroll
    for (int t = 0; t < 8; t++)
        #pragma unroll
        for (int n = 0; n < 2; n++) {
            m0 = fmaxf(m0, fmaxf(acc[t][n][0], acc[t][n][1]));
            m1 = fmaxf(m1, fmaxf(acc[t][n][2], acc[t][n][3]));
        }
    #pragma unroll
    for (int o = 1; o <= 2; o <<= 1) {
        m0 = fmaxf(m0, __shfl_xor_sync(0xffffffffu, m0, o));
        m1 = fmaxf(m1, __shfl_xor_sync(0xffffffffu, m1, o));
    }
    if (tig == 0) { redmax[r0 * 8 + wn] = m0; redmax[r1 * 8 + wn] = m1; }
    __syncthreads();
    float rm0 = redmax[r0 * 8], rm1 = redmax[r1 * 8];
    #pragma unroll
    for (int w = 1; w < 8; w++) {
        rm0 = fmaxf(rm0, redmax[r0 * 8 + w]);
        rm1 = fmaxf(rm1, redmax[r1 * 8 + w]);
    }

    float s0 = 0.f, s1 = 0.f;
    #pragma unroll
    for (int t = 0; t < 8; t++)
        #pragma unroll
        for (int n = 0; n < 2; n++) {
            float e0 = __expf((acc[t][n][0] - rm0) * scale);
            float e1 = __expf((acc[t][n][1] - rm0) * scale);
            float e2 = __expf((acc[t][n][2] - rm1) * scale);
            float e3 = __expf((acc[t][n][3] - rm1) * scale);
            acc[t][n][0] = e0; acc[t][n][1] = e1;
            acc[t][n][2] = e2; acc[t][n][3] = e3;
            s0 += e0 + e1;
            s1 += e2 + e3;
        }
    #pragma unroll
    for (int o = 1; o <= 2; o <<= 1) {
        s0 += __shfl_xor_sync(0xffffffffu, s0, o);
        s1 += __shfl_xor_sync(0xffffffffu, s1, o);
    }
    if (tig == 0) { redsum[r0 * 8 + wn] = s0; redsum[r1 * 8 + wn] = s1; }
    __syncthreads();
    float t0 = 0.f, t1 = 0.f;
    #pragma unroll
    for (int w = 0; w < 8; w++) { t0 += redsum[r0 * 8 + w]; t1 += redsum[r1 * 8 + w]; }
    const float inv0 = __fdividef(1.f, t0);
    const float inv1 = __fdividef(1.f, t1);

    // ---------------- P @ V phase (V streamed into dead K buffers) --------
    const long long row0 = obase + (long long)(qiBlock + r0) * SEQ;
    const long long row1 = obase + (long long)(qiBlock + r1) * SEQ;

    float accO[8][4];
    #pragma unroll
    for (int nf = 0; nf < 8; nf++)
        #pragma unroll
        for (int i = 0; i < 4; i++) accO[nf][i] = 0.f;

    load_v(0, 0);
    #pragma unroll
    for (int t = 0; t < 8; t++) {
        const int buf = t & 1;
        if (t < 7) { load_v(t + 1, (t + 1) & 1); CPA_WAIT1(); }
        else       { CPA_WAIT0(); }

        // normalize P, store attn output, build A-frags (hi/lo)
        float p00 = acc[t][0][0] * inv0, p01 = acc[t][0][1] * inv0;
        float p02 = acc[t][0][2] * inv1, p03 = acc[t][0][3] * inv1;
        float p10 = acc[t][1][0] * inv0, p11 = acc[t][1][1] * inv0;
        float p12 = acc[t][1][2] * inv1, p13 = acc[t][1][3] * inv1;
        {
            const int col = t * 128 + wn * 16 + tig * 2;
            *(float2*)(attn + row0 + col)     = make_float2(p00, p01);
            *(float2*)(attn + row1 + col)     = make_float2(p02, p03);
            *(float2*)(attn + row0 + col + 8) = make_float2(p10, p11);
            *(float2*)(attn + row1 + col + 8) = make_float2(p12, p13);
        }
        uint32_t aPh[4], aPl[4];
        aPh[0] = pack_hi(p00, p01); aPl[0] = pack_lo(p00, p01);
        aPh[1] = pack_hi(p02, p03); aPl[1] = pack_lo(p02, p03);
        aPh[2] = pack_hi(p10, p11); aPl[2] = pack_lo(p10, p11);
        aPh[3] = pack_hi(p12, p13); aPl[3] = pack_lo(p12, p13);

        __syncthreads();   // V tile ready, previous tile reads done

        const uint32_t vh_b = sKhi + buf * SC_KBUF;
        const uint32_t vl_b = sKlo + buf * SC_KBUF;
        #pragma unroll
        for (int nb = 0; nb < 4; nb++) {
            uint32_t off = (uint32_t)((wn * 16 + vkr) * QKP + nb * 16 + vnc) * 2;
            uint32_t bhiV[2][2], bloV[2][2];
            uint32_t r0v, r1v, r2v, r3v;
            LDMX4T(r0v, r1v, r2v, r3v, vh_b + off);
            bhiV[0][0] = r0v; bhiV[0][1] = r1v; bhiV[1][0] = r2v; bhiV[1][1] = r3v;
            LDMX4T(r0v, r1v, r2v, r3v, vl_b + off);
            bloV[0][0] = r0v; bloV[0][1] = r1v; bloV[1][0] = r2v; bloV[1][1] = r3v;
            #pragma unroll
            for (int j = 0; j < 2; j++) {
                const int nf = nb * 2 + j;
                MMA16816(accO[nf], aPh, bhiV[j]);
                MMA16816(accO[nf], aPl, bhiV[j]);
                MMA16816(accO[nf], aPh, bloV[j]);
            }
        }
        __syncthreads();
    }

    // ---------------- cross-warp O reduction + ctx store ----------------
    {
        float* mine = Opart + (wm * 8 + wn) * (16 * 64);
        #pragma unroll
        for (int nf = 0; nf < 8; nf++) {
            const int col = nf * 8 + tig * 2;
            *(float2*)(mine + gid * 64 + col)       = make_float2(accO[nf][0], accO[nf][1]);
            *(float2*)(mine + (gid + 8) * 64 + col) = make_float2(accO[nf][2], accO[nf][3]);
        }
    }
    __syncthreads();
    {
        const int e = tid * 4;
        const int row = e >> 6;          // 0..31
        const int col = e & 63;
        const int wmr = row >> 4, lr = row & 15;
        float4 s = make_float4(0.f, 0.f, 0.f, 0.f);
        #pragma unroll
        for (int w = 0; w < 8; w++) {
            float4 v = *(float4*)(Opart + (wmr * 8 + w) * (16 * 64) + lr * 64 + col);
            s.x += v.x; s.y += v.y; s.z += v.z; s.w += v.w;
        }
        const long long dst = base + (long long)(qiBlock + row) * DMODEL + col;
        __half2 h0, h1, l0, l1;
        h0.x = __float2half(s.x); h0.y = __float2half(s.y);
        l0.x = __float2half(s.x - __half2float(h0.x));
        l0.y = __float2half(s.y - __half2float(h0.y));
        h1.x = __float2half(s.z); h1.y = __float2half(s.w);
        l1.x = __float2half(s.z - __half2float(h1.x));
        l1.y = __float2half(s.w - __half2float(h1.y));
        *(__half2*)(ctx_hi + dst)     = h0;
        *(__half2*)(ctx_hi + dst + 2) = h1;
        *(__half2*)(ctx_lo + dst)     = l0;
        *(__half2*)(ctx_lo + dst + 2) = l1;
    }
}

// ---------------------------------------------------------------------------
// Launcher
// ---------------------------------------------------------------------------
extern "C" void kernel_launch(void* const* d_in, const int* in_sizes, int n_in,
                              void* d_out, int out_size)
{
    (void)in_sizes; (void)n_in; (void)out_size;

    const float* q   = (const float*)d_in[0];
    const float* k   = (const float*)d_in[1];
    const float* v   = (const float*)d_in[2];
    const float* Wq  = (const float*)d_in[3];
    const float* bq  = (const float*)d_in[4];
    const float* Wk  = (const float*)d_in[5];
    const float* bk  = (const float*)d_in[6];
    const float* Wv  = (const float*)d_in[7];
    const float* bv  = (const float*)d_in[8];
    const float* Wfc = (const float*)d_in[9];
    const float* bfc = (const float*)d_in[10];

    float* out  = (float*)d_out;
    float* attn = out + OUT_ELEMS;

    __half *q_hi, *q_lo, *k_hi, *k_lo, *v_hi, *v_lo;
    __half *pWq, *pWk, *pWv, *pWfc;
    __half *qh_hi, *qh_lo, *kh_hi, *kh_lo, *vh_hi, *vh_lo, *ctx_hi, *ctx_lo;
    cudaGetSymbolAddress((void**)&q_hi, g_q_hi);   cudaGetSymbolAddress((void**)&q_lo, g_q_lo);
    cudaGetSymbolAddress((void**)&k_hi, g_k_hi);   cudaGetSymbolAddress((void**)&k_lo, g_k_lo);
    cudaGetSymbolAddress((void**)&v_hi, g_v_hi);   cudaGetSymbolAddress((void**)&v_lo, g_v_lo);
    cudaGetSymbolAddress((void**)&pWq, g_Wq);
    cudaGetSymbolAddress((void**)&pWk, g_Wk);
    cudaGetSymbolAddress((void**)&pWv, g_Wv);
    cudaGetSymbolAddress((void**)&pWfc, g_Wfc);
    cudaGetSymbolAddress((void**)&qh_hi, g_qh_hi); cudaGetSymbolAddress((void**)&qh_lo, g_qh_lo);
    cudaGetSymbolAddress((void**)&kh_hi, g_kh_hi); cudaGetSymbolAddress((void**)&kh_lo, g_kh_lo);
    cudaGetSymbolAddress((void**)&vh_hi, g_vh_hi); cudaGetSymbolAddress((void**)&vh_lo, g_vh_lo);
    cudaGetSymbolAddress((void**)&ctx_hi, g_ctx_hi); cudaGetSymbolAddress((void**)&ctx_lo, g_ctx_lo);

    cudaFuncSetAttribute(proj_gemm_async<false>,
                         cudaFuncAttributeMaxDynamicSharedMemorySize, PRJ_SMEM);
    cudaFuncSetAttribute(proj_gemm_async<true>,
                         cudaFuncAttributeMaxDynamicSharedMemorySize, PRJ_SMEM);
    cudaFuncSetAttribute(fused_attn,
                         cudaFuncAttributeMaxDynamicSharedMemorySize, SC_SMEM);

    const int nBig = MROWS * DMODEL;
    const int nW   = DMODEL * DMODEL;
    split_kernel<<<nBig / 1024, 256>>>(q, q_hi, q_lo);
    split_kernel<<<nBig / 1024, 256>>>(k, k_hi, k_lo);
    split_kernel<<<nBig / 1024, 256>>>(v, v_hi, v_lo);
    convert_kernel<<<nW / 1024, 256>>>(Wq,  pWq);
    convert_kernel<<<nW / 1024, 256>>>(Wk,  pWk);
    convert_kernel<<<nW / 1024, 256>>>(Wv,  pWv);
    convert_kernel<<<nW / 1024, 256>>>(Wfc, pWfc);

    dim3 gProj(DMODEL / 128, MROWS / 64);            // (8, 128)
    proj_gemm_async<false><<<gProj, 256, PRJ_SMEM>>>(
        q_hi, q_lo, pWq, bq, nullptr, qh_hi, qh_lo, MROWS, DMODEL, DMODEL);
    proj_gemm_async<false><<<gProj, 256, PRJ_SMEM>>>(
        k_hi, k_lo, pWk, bk, nullptr, kh_hi, kh_lo, MROWS, DMODEL, DMODEL);
    proj_gemm_async<false><<<gProj, 256, PRJ_SMEM>>>(
        v_hi, v_lo, pWv, bv, nullptr, vh_hi, vh_lo, MROWS, DMODEL, DMODEL);

    dim3 gAttn(SEQ / 32, BATCH * NHEAD);             // (32, 128)
    fused_attn<<<gAttn, 512, SC_SMEM>>>(qh_hi, qh_lo, kh_hi, kh_lo,
                                        vh_hi, vh_lo, attn, ctx_hi, ctx_lo);

    proj_gemm_async<true><<<gProj, 256, PRJ_SMEM>>>(
        ctx_hi, ctx_lo, pWfc, bfc, out, nullptr, nullptr, MROWS, DMODEL, DMODEL);
}

// round 15
// speedup vs baseline: 1.2739x; 1.0283x over previous
#include <cuda_runtime.h>
#include <cuda_fp16.h>
#include <math.h>
#include <stdint.h>

// ---------------------------------------------------------------------------
// MultiHeadAttention: B=8, L=1024, D_MODEL=1024, H=16, Dk=64
// Round 15: round-14 (1015us) + ONE change: fused_attn S-phase Q fragments
// hoisted out of the K-tile loop (Q tile is loop-invariant; saves 56/64
// Q-ldmatrix per warp). Everything else identical.
// d_out = [ out (8*1024*1024 f32) | attn_flat ((16*8)*1024*1024 f32) ]
// ---------------------------------------------------------------------------

#define BATCH 8
#define SEQ   1024
#define DMODEL 1024
#define NHEAD 16
#define DK    64
#define MROWS (BATCH * SEQ)          // 8192
#define OUT_ELEMS (MROWS * DMODEL)   // 8388608

#define BKP  40    // 32 + 8 pad (fp16) A tiles (proj)
#define BNP  136   // 128 + 8 pad  B tiles (proj)
#define QKP  72    // 64 + 8 pad   attn Q/K/V tiles

// ---------------- static scratch (no allocations) ----------------
__device__ __half g_q_hi[MROWS * DMODEL],  g_q_lo[MROWS * DMODEL];
__device__ __half g_k_hi[MROWS * DMODEL],  g_k_lo[MROWS * DMODEL];
__device__ __half g_v_hi[MROWS * DMODEL],  g_v_lo[MROWS * DMODEL];
__device__ __half g_Wq[DMODEL * DMODEL];
__device__ __half g_Wk[DMODEL * DMODEL];
__device__ __half g_Wv[DMODEL * DMODEL];
__device__ __half g_Wfc[DMODEL * DMODEL];
__device__ __half g_qh_hi[MROWS * DMODEL], g_qh_lo[MROWS * DMODEL];
__device__ __half g_kh_hi[MROWS * DMODEL], g_kh_lo[MROWS * DMODEL];
__device__ __half g_vh_hi[MROWS * DMODEL], g_vh_lo[MROWS * DMODEL];
__device__ __half g_ctx_hi[MROWS * DMODEL], g_ctx_lo[MROWS * DMODEL];

// ---------------------------------------------------------------------------
// PTX helpers
// ---------------------------------------------------------------------------
__device__ __forceinline__ uint32_t smem_u32(const void* p) {
    return (uint32_t)__cvta_generic_to_shared(p);
}

#define LDMX4(r0,r1,r2,r3,addr) \
    asm volatile("ldmatrix.sync.aligned.m8n8.x4.shared.b16 {%0,%1,%2,%3}, [%4];" \
        : "=r"(r0), "=r"(r1), "=r"(r2), "=r"(r3) : "r"(addr))

#define LDMX4T(r0,r1,r2,r3,addr) \
    asm volatile("ldmatrix.sync.aligned.m8n8.x4.trans.shared.b16 {%0,%1,%2,%3}, [%4];" \
        : "=r"(r0), "=r"(r1), "=r"(r2), "=r"(r3) : "r"(addr))

#define MMA16816(c, a, b) \
    asm volatile("mma.sync.aligned.m16n8k16.row.col.f32.f16.f16.f32 " \
        "{%0,%1,%2,%3}, {%4,%5,%6,%7}, {%8,%9}, {%0,%1,%2,%3};" \
        : "+f"((c)[0]), "+f"((c)[1]), "+f"((c)[2]), "+f"((c)[3]) \
        : "r"((a)[0]), "r"((a)[1]), "r"((a)[2]), "r"((a)[3]), \
          "r"((b)[0]), "r"((b)[1]))

#define CPA16(dst, src) \
    asm volatile("cp.async.cg.shared.global [%0], [%1], 16;" :: "r"(dst), "l"(src))
#define CPA_COMMIT() asm volatile("cp.async.commit_group;")
#define CPA_WAIT1()  asm volatile("cp.async.wait_group 1;")
#define CPA_WAIT0()  asm volatile("cp.async.wait_group 0;")

__device__ __forceinline__ uint32_t pack_hi(float x, float y) {
    __half2 h;
    h.x = __float2half(x); h.y = __float2half(y);
    return *(uint32_t*)&h;
}
__device__ __forceinline__ uint32_t pack_lo(float x, float y) {
    __half hx = __float2half(x), hy = __float2half(y);
    __half2 l;
    l.x = __float2half(x - __half2float(hx));
    l.y = __float2half(y - __half2float(hy));
    return *(uint32_t*)&l;
}

// ---------------------------------------------------------------------------
// Elementwise pre-split: f32 -> (hi, lo) fp16
// ---------------------------------------------------------------------------
__global__ __launch_bounds__(256) void split_kernel(
    const float* __restrict__ in, __half* __restrict__ hi,
    __half* __restrict__ lo)
{
    const int i = (blockIdx.x * 256 + threadIdx.x) * 4;
    float4 v = *(const float4*)(in + i);
    __half h0 = __float2half(v.x);
    __half h1 = __float2half(v.y);
    __half h2 = __float2half(v.z);
    __half h3 = __float2half(v.w);
    __half2 hp0; hp0.x = h0; hp0.y = h1;
    __half2 hp1; hp1.x = h2; hp1.y = h3;
    *(__half2*)(hi + i)     = hp0;
    *(__half2*)(hi + i + 2) = hp1;
    __half2 lp0, lp1;
    lp0.x = __float2half(v.x - __half2float(h0));
    lp0.y = __float2half(v.y - __half2float(h1));
    lp1.x = __float2half(v.z - __half2float(h2));
    lp1.y = __float2half(v.w - __half2float(h3));
    *(__half2*)(lo + i)     = lp0;
    *(__half2*)(lo + i + 2) = lp1;
}

// Single fp16 convert (weights)
__global__ __launch_bounds__(256) void convert_kernel(
    const float* __restrict__ in, __half* __restrict__ outp)
{
    const int i = (blockIdx.x * 256 + threadIdx.x) * 4;
    float4 v = *(const float4*)(in + i);
    __half2 p0, p1;
    p0.x = __float2half(v.x); p0.y = __float2half(v.y);
    p1.x = __float2half(v.z); p1.y = __float2half(v.w);
    *(__half2*)(outp + i)     = p0;
    *(__half2*)(outp + i + 2) = p1;
}

// ---------------------------------------------------------------------------
// Projection GEMM — 256 threads, 64x128 tile, BK=32, 2-stage cp.async,
// 2 blocks/SM. A = (hi+lo) fp16 split, B = single fp16 -> 2 MMAs/k-step.
// (verified round-14 version, unchanged)
// ---------------------------------------------------------------------------
#define PRJ_ABUF (64 * BKP * 2)            // 5120
#define PRJ_BBUF (32 * BNP * 2)            // 8704
#define PRJ_OAHI 0
#define PRJ_OALO (2 * PRJ_ABUF)            // 10240
#define PRJ_OB   (4 * PRJ_ABUF)            // 20480
#define PRJ_SMEM (PRJ_OB + 2 * PRJ_BBUF)   // 37888

template<bool F32OUT>
__global__ __launch_bounds__(256, 2) void proj_gemm_async(
    const __half* __restrict__ Ahi_g, const __half* __restrict__ Alo_g,
    const __half* __restrict__ B_g,
    const float* __restrict__ bias,
    float* __restrict__ Cf, __half* __restrict__ Chi, __half* __restrict__ Clo,
    int M, int N, int K)
{
    extern __shared__ __align__(16) char dynsmem[];
    const uint32_t sBase = smem_u32(dynsmem);
    const uint32_t sAhi = sBase + PRJ_OAHI;
    const uint32_t sAlo = sBase + PRJ_OALO;
    const uint32_t sB   = sBase + PRJ_OB;

    const int tid = threadIdx.x;
    const int warp = tid >> 5, lane = tid & 31;
    const int wm = warp & 1, wn = warp >> 1;       // 2 x 4
    const int rowBlock = blockIdx.y * 64;
    const int colBlock = blockIdx.x * 128;

    const int arow = tid >> 2, aseg = tid & 3;
    const long long aGbase = (long long)(rowBlock + arow) * K + aseg * 8;
    const uint32_t aSoff = (uint32_t)(arow * BKP + aseg * 8) * 2;
    const int brow0 = tid >> 4,          bseg0 = tid & 15;
    const int brow1 = (tid + 256) >> 4,  bseg1 = (tid + 256) & 15;
    const long long bGbase0 = (long long)brow0 * N + colBlock + bseg0 * 8;
    const long long bGbase1 = (long long)brow1 * N + colBlock + bseg1 * 8;
    const uint32_t bSoff0 = (uint32_t)(brow0 * BNP + bseg0 * 8) * 2;
    const uint32_t bSoff1 = (uint32_t)(brow1 * BNP + bseg1 * 8) * 2;

    auto load_tile = [&](int kt, int buf) {
        const long long ka  = aGbase + kt * 32;
        const long long kb0 = bGbase0 + (long long)(kt * 32) * N;
        const long long kb1 = bGbase1 + (long long)(kt * 32) * N;
        CPA16(sAhi + buf * PRJ_ABUF + aSoff, Ahi_g + ka);
        CPA16(sAlo + buf * PRJ_ABUF + aSoff, Alo_g + ka);
        CPA16(sB + buf * PRJ_BBUF + bSoff0, B_g + kb0);
        CPA16(sB + buf * PRJ_BBUF + bSoff1, B_g + kb1);
        CPA_COMMIT();
    };

    float acc[2][4][4];
    #pragma unroll
    for (int i = 0; i < 2; i++)
        #pragma unroll
        for (int j = 0; j < 4; j++)
            #pragma unroll
            for (int l = 0; l < 4; l++) acc[i][j][l] = 0.f;

    const int alr = (lane & 7) + ((lane >> 3) & 1) * 8;
    const int alc = (lane >> 4) * 8;
    const int bkr = (lane & 7) + ((lane >> 3) & 1) * 8;
    const int bnc = ((lane >> 4) & 1) * 8;

    const int KT = K / 32;
    load_tile(0, 0);
    for (int kt = 0; kt < KT; kt++) {
        const int buf = kt & 1;
        if (kt + 1 < KT) { load_tile(kt + 1, (kt + 1) & 1); CPA_WAIT1(); }
        else             { CPA_WAIT0(); }
        __syncthreads();

        const uint32_t bAhi = sAhi + buf * PRJ_ABUF;
        const uint32_t bAlo = sAlo + buf * PRJ_ABUF;
        const uint32_t bB   = sB + buf * PRJ_BBUF;

        #pragma unroll
        for (int kk = 0; kk < 32; kk += 16) {
            uint32_t ahi[2][4], alo[2][4];
            #pragma unroll
            for (int ms = 0; ms < 2; ms++) {
                uint32_t off = (uint32_t)((wm * 32 + ms * 16 + alr) * BKP + kk + alc) * 2;
                LDMX4(ahi[ms][0], ahi[ms][1], ahi[ms][2], ahi[ms][3], bAhi + off);
                LDMX4(alo[ms][0], alo[ms][1], alo[ms][2], alo[ms][3], bAlo + off);
            }
            uint32_t bfr[4][2];
            #pragma unroll
            for (int np = 0; np < 2; np++) {
                uint32_t r0, r1, r2, r3;
                uint32_t off = (uint32_t)((kk + bkr) * BNP + wn * 32 + np * 16 + bnc) * 2;
                LDMX4T(r0, r1, r2, r3, bB + off);
                bfr[np*2][0] = r0; bfr[np*2][1] = r1;
                bfr[np*2+1][0] = r2; bfr[np*2+1][1] = r3;
            }
            #pragma unroll
            for (int ms = 0; ms < 2; ms++)
                #pragma unroll
                for (int ns = 0; ns < 4; ns++) {
                    MMA16816(acc[ms][ns], ahi[ms], bfr[ns]);
                    MMA16816(acc[ms][ns], alo[ms], bfr[ns]);
                }
        }
        __syncthreads();
    }

    const int gid = lane >> 2, tig = lane & 3;
    #pragma unroll
    for (int ms = 0; ms < 2; ms++)
        #pragma unroll
        for (int ns = 0; ns < 4; ns++) {
            const int row = rowBlock + wm * 32 + ms * 16 + gid;
            const int col = colBlock + wn * 32 + ns * 8 + tig * 2;
            float2 bz = *(const float2*)(bias + col);
            float* a = acc[ms][ns];
            float f0 = a[0] + bz.x, f1 = a[1] + bz.y;
            float f2 = a[2] + bz.x, f3 = a[3] + bz.y;
            if (F32OUT) {
                *(float2*)(Cf + (long long)row * N + col)       = make_float2(f0, f1);
                *(float2*)(Cf + (long long)(row + 8) * N + col) = make_float2(f2, f3);
            } else {
                __half2 h, l;
                h.x = __float2half(f0); h.y = __float2half(f1);
                l.x = __float2half(f0 - __half2float(h.x));
                l.y = __float2half(f1 - __half2float(h.y));
                *(__half2*)(Chi + (long long)row * N + col) = h;
                *(__half2*)(Clo + (long long)row * N + col) = l;
                h.x = __float2half(f2); h.y = __float2half(f3);
                l.x = __float2half(f2 - __half2float(h.x));
                l.y = __float2half(f3 - __half2float(h.y));
                *(__half2*)(Chi + (long long)(row + 8) * N + col) = h;
                *(__half2*)(Clo + (long long)(row + 8) * N + col) = l;
            }
        }
}

// ---------------------------------------------------------------------------
// FUSED attention — round-14 512-thread structure, fp16 hi/lo operands,
// CHANGE: Q fragments hoisted out of the S-phase kt loop (loop-invariant).
// ---------------------------------------------------------------------------
#define SC_QBUF (32 * QKP * 2)            // 4608
#define SC_KBUF (128 * QKP * 2)           // 18432 per buffer
#define SC_OQHI 0
#define SC_OQLO SC_QBUF
#define SC_OKHI (2 * SC_QBUF)             // 9216
#define SC_OKLO (SC_OKHI + 2 * SC_KBUF)   // 46080
#define SC_ORMAX (SC_OKLO + 2 * SC_KBUF)  // 82944
#define SC_ORSUM (SC_ORMAX + 1024)        // 83968
#define SC_OPART (SC_ORSUM + 1024)        // 84992
#define SC_SMEM  (SC_OPART + 16 * 16 * 64 * 4)   // 150528

__global__ __launch_bounds__(512, 1) void fused_attn(
    const __half* __restrict__ qh_hi, const __half* __restrict__ qh_lo,
    const __half* __restrict__ kh_hi, const __half* __restrict__ kh_lo,
    const __half* __restrict__ vh_hi, const __half* __restrict__ vh_lo,
    float* __restrict__ attn,
    __half* __restrict__ ctx_hi, __half* __restrict__ ctx_lo)
{
    extern __shared__ __align__(16) char dynsmem[];
    const uint32_t sBase = smem_u32(dynsmem);
    const uint32_t sQhi = sBase + SC_OQHI;
    const uint32_t sQlo = sBase + SC_OQLO;
    const uint32_t sKhi = sBase + SC_OKHI;   // aliased by V in PV phase
    const uint32_t sKlo = sBase + SC_OKLO;
    float* redmax = (float*)(dynsmem + SC_ORMAX);
    float* redsum = (float*)(dynsmem + SC_ORSUM);
    float* Opart  = (float*)(dynsmem + SC_OPART);

    const int tid = threadIdx.x;
    const int warp = tid >> 5, lane = tid & 31;
    const int wm = warp & 1, wn = warp >> 1;
    const int qiBlock = blockIdx.x * 32;
    const int bh = blockIdx.y;                    // h*8 + b
    const int b = bh & 7, h = bh >> 3;

    const long long base  = (long long)b * SEQ * DMODEL + h * DK;
    const long long obase = (long long)bh * SEQ * SEQ;

    // Q load (once)
    {
        const int chunk = tid & 255;
        const int qr = chunk >> 3, qs = chunk & 7;
        const uint32_t dst = (tid < 256 ? sQhi : sQlo) + (uint32_t)(qr * QKP + qs * 8) * 2;
        const __half* src = (tid < 256 ? qh_hi : qh_lo) +
            base + (long long)(qiBlock + qr) * DMODEL + qs * 8;
        CPA16(dst, src);
    }

    auto load_k = [&](int kt, int buf) {
        #pragma unroll
        for (int p = 0; p < 2; p++) {
            const int chunk = tid + p * 512;
            const int kr = chunk >> 3, ks = chunk & 7;
            const long long g = base + (long long)(kt * 128 + kr) * DMODEL + ks * 8;
            const uint32_t so = (uint32_t)(kr * QKP + ks * 8) * 2;
            CPA16(sKhi + buf * SC_KBUF + so, kh_hi + g);
            CPA16(sKlo + buf * SC_KBUF + so, kh_lo + g);
        }
        CPA_COMMIT();
    };
    auto load_v = [&](int kt, int buf) {
        #pragma unroll
        for (int p = 0; p < 2; p++) {
            const int chunk = tid + p * 512;
            const int kr = chunk >> 3, ks = chunk & 7;
            const long long g = base + (long long)(kt * 128 + kr) * DMODEL + ks * 8;
            const uint32_t so = (uint32_t)(kr * QKP + ks * 8) * 2;
            CPA16(sKhi + buf * SC_KBUF + so, vh_hi + g);
            CPA16(sKlo + buf * SC_KBUF + so, vh_lo + g);
        }
        CPA_COMMIT();
    };

    float acc[8][2][4];
    #pragma unroll
    for (int t = 0; t < 8; t++)
        #pragma unroll
        for (int n = 0; n < 2; n++)
            #pragma unroll
            for (int i = 0; i < 4; i++) acc[t][n][i] = 0.f;

    const int alr = (lane & 7) + ((lane >> 3) & 1) * 8;
    const int alc = (lane >> 4) * 8;
    const int bnr = (lane & 7) + ((lane >> 4) & 1) * 8;
    const int bkc = ((lane >> 3) & 1) * 8;
    const int vkr = (lane & 7) + ((lane >> 3) & 1) * 8;   // trans row (ki)
    const int vnc = ((lane >> 4) & 1) * 8;                // trans col (d)

    // ---------------- S = Q K^T phase ----------------
    // Q fragments are loop-invariant across kt: load ONCE after first wait.
    uint32_t qfh[4][4], qfl[4][4];
    load_k(0, 0);
    #pragma unroll
    for (int kt = 0; kt < 8; kt++) {
        const int buf = kt & 1;
        if (kt < 7) { load_k(kt + 1, (kt + 1) & 1); CPA_WAIT1(); }
        else        { CPA_WAIT0(); }
        __syncthreads();

        if (kt == 0) {
            #pragma unroll
            for (int k4 = 0; k4 < 4; k4++) {
                uint32_t off = (uint32_t)((wm * 16 + alr) * QKP + k4 * 16 + alc) * 2;
                LDMX4(qfh[k4][0], qfh[k4][1], qfh[k4][2], qfh[k4][3], sQhi + off);
                LDMX4(qfl[k4][0], qfl[k4][1], qfl[k4][2], qfl[k4][3], sQlo + off);
            }
        }

        const uint32_t kh_b = sKhi + buf * SC_KBUF;
        const uint32_t kl_b = sKlo + buf * SC_KBUF;
        #pragma unroll
        for (int k4 = 0; k4 < 4; k4++) {
            const int kk = k4 * 16;
            uint32_t bhi[2][2], blo[2][2];
            {
                uint32_t off = (uint32_t)((wn * 16 + bnr) * QKP + kk + bkc) * 2;
                uint32_t r0, r1, r2, r3;
                LDMX4(r0, r1, r2, r3, kh_b + off);
                bhi[0][0] = r0; bhi[0][1] = r1; bhi[1][0] = r2; bhi[1][1] = r3;
                LDMX4(r0, r1, r2, r3, kl_b + off);
                blo[0][0] = r0; blo[0][1] = r1; blo[1][0] = r2; blo[1][1] = r3;
            }
            #pragma unroll
            for (int nf = 0; nf < 2; nf++) {
                MMA16816(acc[kt][nf], qfh[k4], bhi[nf]);
                MMA16816(acc[kt][nf], qfl[k4], bhi[nf]);
                MMA16816(acc[kt][nf], qfh[k4], blo[nf]);
            }
        }
        __syncthreads();
    }

    // ---------------- softmax ----------------
    const int gid = lane >> 2, tig = lane & 3;
    const int r0 = wm * 16 + gid;
    const int r1 = r0 + 8;
    const float scale = 0.125f;

    float m0 = -1e30f, m1 = -1e30f;
    #pragma unroll
    for (int t = 0; t < 8; t++)
        #pragma unroll
        for (int n = 0; n < 2; n++) {
            m0 = fmaxf(m0, fmaxf(acc[t][n][0], acc[t][n][1]));
            m1 = fmaxf(m1, fmaxf(acc[t][n][2], acc[t][n][3]));
        }
    #pragma unroll
    for (int o = 1; o <= 2; o <<= 1) {
        m0 = fmaxf(m0, __shfl_xor_sync(0xffffffffu, m0, o));
        m1 = fmaxf(m1, __shfl_xor_sync(0xffffffffu, m1, o));
    }
    if (tig == 0) { redmax[r0 * 8 + wn] = m0; redmax[r1 * 8 + wn] = m1; }
    __syncthreads();
    float rm0 = redmax[r0 * 8], rm1 = redmax[r1 * 8];
    #pragma unroll
    for (int w = 1; w < 8; w++) {
        rm0 = fmaxf(rm0, redmax[r0 * 8 + w]);
        rm1 = fmaxf(rm1, redmax[r1 * 8 + w]);
    }

    float s0 = 0.f, s1 = 0.f;
    #pragma unroll
    for (int t = 0; t < 8; t++)
        #pragma unroll
        for (int n = 0; n < 2; n++) {
            float e0 = __expf((acc[t][n][0] - rm0) * scale);
            float e1 = __expf((acc[t][n][1] - rm0) * scale);
            float e2 = __expf((acc[t][n][2] - rm1) * scale);
            float e3 = __expf((acc[t][n][3] - rm1) * scale);
            acc[t][n][0] = e0; acc[t][n][1] = e1;
            acc[t][n][2] = e2; acc[t][n][3] = e3;
            s0 += e0 + e1;
            s1 += e2 + e3;
        }
    #pragma unroll
    for (int o = 1; o <= 2; o <<= 1) {
        s0 += __shfl_xor_sync(0xffffffffu, s0, o);
        s1 += __shfl_xor_sync(0xffffffffu, s1, o);
    }
    if (tig == 0) { redsum[r0 * 8 + wn] = s0; redsum[r1 * 8 + wn] = s1; }
    __syncthreads();
    float t0 = 0.f, t1 = 0.f;
    #pragma unroll
    for (int w = 0; w < 8; w++) { t0 += redsum[r0 * 8 + w]; t1 += redsum[r1 * 8 + w]; }
    const float inv0 = __fdividef(1.f, t0);
    const float inv1 = __fdividef(1.f, t1);

    // ---------------- P @ V phase (V streamed into dead K buffers) --------
    const long long row0 = obase + (long long)(qiBlock + r0) * SEQ;
    const long long row1 = obase + (long long)(qiBlock + r1) * SEQ;

    float accO[8][4];
    #pragma unroll
    for (int nf = 0; nf < 8; nf++)
        #pragma unroll
        for (int i = 0; i < 4; i++) accO[nf][i] = 0.f;

    load_v(0, 0);
    #pragma unroll
    for (int t = 0; t < 8; t++) {
        const int buf = t & 1;
        if (t < 7) { load_v(t + 1, (t + 1) & 1); CPA_WAIT1(); }
        else       { CPA_WAIT0(); }

        // normalize P, store attn output, build A-frags (hi/lo)
        float p00 = acc[t][0][0] * inv0, p01 = acc[t][0][1] * inv0;
        float p02 = acc[t][0][2] * inv1, p03 = acc[t][0][3] * inv1;
        float p10 = acc[t][1][0] * inv0, p11 = acc[t][1][1] * inv0;
        float p12 = acc[t][1][2] * inv1, p13 = acc[t][1][3] * inv1;
        {
            const int col = t * 128 + wn * 16 + tig * 2;
            *(float2*)(attn + row0 + col)     = make_float2(p00, p01);
            *(float2*)(attn + row1 + col)     = make_float2(p02, p03);
            *(float2*)(attn + row0 + col + 8) = make_float2(p10, p11);
            *(float2*)(attn + row1 + col + 8) = make_float2(p12, p13);
        }
        uint32_t aPh[4], aPl[4];
        aPh[0] = pack_hi(p00, p01); aPl[0] = pack_lo(p00, p01);
        aPh[1] = pack_hi(p02, p03); aPl[1] = pack_lo(p02, p03);
        aPh[2] = pack_hi(p10, p11); aPl[2] = pack_lo(p10, p11);
        aPh[3] = pack_hi(p12, p13); aPl[3] = pack_lo(p12, p13);

        __syncthreads();   // V tile ready, previous tile reads done

        const uint32_t vh_b = sKhi + buf * SC_KBUF;
        const uint32_t vl_b = sKlo + buf * SC_KBUF;
        #pragma unroll
        for (int nb = 0; nb < 4; nb++) {
            uint32_t off = (uint32_t)((wn * 16 + vkr) * QKP + nb * 16 + vnc) * 2;
            uint32_t bhiV[2][2], bloV[2][2];
            uint32_t r0v, r1v, r2v, r3v;
            LDMX4T(r0v, r1v, r2v, r3v, vh_b + off);
            bhiV[0][0] = r0v; bhiV[0][1] = r1v; bhiV[1][0] = r2v; bhiV[1][1] = r3v;
            LDMX4T(r0v, r1v, r2v, r3v, vl_b + off);
            bloV[0][0] = r0v; bloV[0][1] = r1v; bloV[1][0] = r2v; bloV[1][1] = r3v;
            #pragma unroll
            for (int j = 0; j < 2; j++) {
                const int nf = nb * 2 + j;
                MMA16816(accO[nf], aPh, bhiV[j]);
                MMA16816(accO[nf], aPl, bhiV[j]);
                MMA16816(accO[nf], aPh, bloV[j]);
            }
        }
        __syncthreads();
    }

    // ---------------- cross-warp O reduction + ctx store ----------------
    {
        float* mine = Opart + (wm * 8 + wn) * (16 * 64);
        #pragma unroll
        for (int nf = 0; nf < 8; nf++) {
            const int col = nf * 8 + tig * 2;
            *(float2*)(mine + gid * 64 + col)       = make_float2(accO[nf][0], accO[nf][1]);
            *(float2*)(mine + (gid + 8) * 64 + col) = make_float2(accO[nf][2], accO[nf][3]);
        }
    }
    __syncthreads();
    {
        const int e = tid * 4;
        const int row = e >> 6;          // 0..31
        const int col = e & 63;
        const int wmr = row >> 4, lr = row & 15;
        float4 s = make_float4(0.f, 0.f, 0.f, 0.f);
        #pragma unroll
        for (int w = 0; w < 8; w++) {
            float4 v = *(float4*)(Opart + (wmr * 8 + w) * (16 * 64) + lr * 64 + col);
            s.x += v.x; s.y += v.y; s.z += v.z; s.w += v.w;
        }
        const long long dst = base + (long long)(qiBlock + row) * DMODEL + col;
        __half2 h0, h1, l0, l1;
        h0.x = __float2half(s.x); h0.y = __float2half(s.y);
        l0.x = __float2half(s.x - __half2float(h0.x));
        l0.y = __float2half(s.y - __half2float(h0.y));
        h1.x = __float2half(s.z); h1.y = __float2half(s.w);
        l1.x = __float2half(s.z - __half2float(h1.x));
        l1.y = __float2half(s.w - __half2float(h1.y));
        *(__half2*)(ctx_hi + dst)     = h0;
        *(__half2*)(ctx_hi + dst + 2) = h1;
        *(__half2*)(ctx_lo + dst)     = l0;
        *(__half2*)(ctx_lo + dst + 2) = l1;
    }
}

// ---------------------------------------------------------------------------
// Launcher
// ---------------------------------------------------------------------------
extern "C" void kernel_launch(void* const* d_in, const int* in_sizes, int n_in,
                              void* d_out, int out_size)
{
    (void)in_sizes; (void)n_in; (void)out_size;

    const float* q   = (const float*)d_in[0];
    const float* k   = (const float*)d_in[1];
    const float* v   = (const float*)d_in[2];
    const float* Wq  = (const float*)d_in[3];
    const float* bq  = (const float*)d_in[4];
    const float* Wk  = (const float*)d_in[5];
    const float* bk  = (const float*)d_in[6];
    const float* Wv  = (const float*)d_in[7];
    const float* bv  = (const float*)d_in[8];
    const float* Wfc = (const float*)d_in[9];
    const float* bfc = (const float*)d_in[10];

    float* out  = (float*)d_out;
    float* attn = out + OUT_ELEMS;

    __half *q_hi, *q_lo, *k_hi, *k_lo, *v_hi, *v_lo;
    __half *pWq, *pWk, *pWv, *pWfc;
    __half *qh_hi, *qh_lo, *kh_hi, *kh_lo, *vh_hi, *vh_lo, *ctx_hi, *ctx_lo;
    cudaGetSymbolAddress((void**)&q_hi, g_q_hi);   cudaGetSymbolAddress((void**)&q_lo, g_q_lo);
    cudaGetSymbolAddress((void**)&k_hi, g_k_hi);   cudaGetSymbolAddress((void**)&k_lo, g_k_lo);
    cudaGetSymbolAddress((void**)&v_hi, g_v_hi);   cudaGetSymbolAddress((void**)&v_lo, g_v_lo);
    cudaGetSymbolAddress((void**)&pWq, g_Wq);
    cudaGetSymbolAddress((void**)&pWk, g_Wk);
    cudaGetSymbolAddress((void**)&pWv, g_Wv);
    cudaGetSymbolAddress((void**)&pWfc, g_Wfc);
    cudaGetSymbolAddress((void**)&qh_hi, g_qh_hi); cudaGetSymbolAddress((void**)&qh_lo, g_qh_lo);
    cudaGetSymbolAddress((void**)&kh_hi, g_kh_hi); cudaGetSymbolAddress((void**)&kh_lo, g_kh_lo);
    cudaGetSymbolAddress((void**)&vh_hi, g_vh_hi); cudaGetSymbolAddress((void**)&vh_lo, g_vh_lo);
    cudaGetSymbolAddress((void**)&ctx_hi, g_ctx_hi); cudaGetSymbolAddress((void**)&ctx_lo, g_ctx_lo);

    cudaFuncSetAttribute(proj_gemm_async<false>,
                         cudaFuncAttributeMaxDynamicSharedMemorySize, PRJ_SMEM);
    cudaFuncSetAttribute(proj_gemm_async<true>,
                         cudaFuncAttributeMaxDynamicSharedMemorySize, PRJ_SMEM);
    cudaFuncSetAttribute(fused_attn,
                         cudaFuncAttributeMaxDynamicSharedMemorySize, SC_SMEM);

    const int nBig = MROWS * DMODEL;
    const int nW   = DMODEL * DMODEL;
    split_kernel<<<nBig / 1024, 256>>>(q, q_hi, q_lo);
    split_kernel<<<nBig / 1024, 256>>>(k, k_hi, k_lo);
    split_kernel<<<nBig / 1024, 256>>>(v, v_hi, v_lo);
    convert_kernel<<<nW / 1024, 256>>>(Wq,  pWq);
    convert_kernel<<<nW / 1024, 256>>>(Wk,  pWk);
    convert_kernel<<<nW / 1024, 256>>>(Wv,  pWv);
    convert_kernel<<<nW / 1024, 256>>>(Wfc, pWfc);

    dim3 gProj(DMODEL / 128, MROWS / 64);            // (8, 128)
    proj_gemm_async<false><<<gProj, 256, PRJ_SMEM>>>(
        q_hi, q_lo, pWq, bq, nullptr, qh_hi, qh_lo, MROWS, DMODEL, DMODEL);
    proj_gemm_async<false><<<gProj, 256, PRJ_SMEM>>>(
        k_hi, k_lo, pWk, bk, nullptr, kh_hi, kh_lo, MROWS, DMODEL, DMODEL);
    proj_gemm_async<false><<<gProj, 256, PRJ_SMEM>>>(
        v_hi, v_lo, pWv, bv, nullptr, vh_hi, vh_lo, MROWS, DMODEL, DMODEL);

    dim3 gAttn(SEQ / 32, BATCH * NHEAD);             // (32, 128)
    fused_attn<<<gAttn, 512, SC_SMEM>>>(qh_hi, qh_lo, kh_hi, kh_lo,
                                        vh_hi, vh_lo, attn, ctx_hi, ctx_lo);

    proj_gemm_async<true><<<gProj, 256, PRJ_SMEM>>>(
        ctx_hi, ctx_lo, pWfc, bfc, out, nullptr, nullptr, MROWS, DMODEL, DMODEL);
}